// round 9
// baseline (speedup 1.0000x reference)
#include <cuda_runtime.h>
#include <cstdint>

// Problem constants (fixed shapes from setup_inputs)
#define B_   512
#define C_   100
#define F_   224
#define E_   8192
#define H_   4
#define I_   28
#define INPUTS_ (F_ * I_)          // 6272 == x_b cols, no padding needed
#define FE_  (F_ * E_)             // 1,835,008
#define FE4_ (FE_ / 4)             // 458,752
#define HASH_BLOCKS  B_            // 512
#define BUILD_BLOCKS (FE4_ / 256)  // 1792 (8 blocks per filter)
#define ACCUM_BLOCKS B_            // 512
#define XWORDS_ (INPUTS_ / 32)     // 196

// Scratch (device globals: allocation-free per harness rules)
// negw[(f*E + e)] : uint4 whose bit c (across 4 words) set <=> table[c][f][e] < 0
__device__ uint32_t g_negw[F_ * E_ * 4];          // 29.36 MB
__device__ int4     g_hashes[B_ * F_];            // 1.8 MB
__device__ int      g_fdone[F_];                  // build blocks done per filter
__device__ int      g_hash_done;                  // hash blocks done

__device__ __forceinline__ int ld_acquire_gpu(const int* p) {
    int v;
    asm volatile("ld.acquire.gpu.b32 %0, [%1];" : "=r"(v) : "l"(p) : "memory");
    return v;
}

// ---------------------------------------------------------------------------
// Zero the progress flags (must run before each fused launch; graph-safe).
// ---------------------------------------------------------------------------
__global__ void init_flags_kernel()
{
    if (threadIdx.x < F_) g_fdone[threadIdx.x] = 0;
    if (threadIdx.x == 0) g_hash_done = 0;
}

// ---------------------------------------------------------------------------
// Fully fused pipeline. Bid order = dispatch order:
//   [0, 512)        hash role   : H3 hashes for one batch row each
//   [512, 2304)     build role  : stream 734MB table -> 100-bit sign masks;
//                                 block covers exactly filter f=(bid-512)/8
//   [2304, 2816)    accum role  : per-warp waits on g_fdone[f] then consumes;
//                                 hides entirely under the build DRAM stream
// ---------------------------------------------------------------------------
__global__ void __launch_bounds__(256)
fused_pipeline_kernel(const float* __restrict__ table,
                      const int*   __restrict__ x_b,
                      const int*   __restrict__ input_order,
                      const int*   __restrict__ hash_values,
                      const float* __restrict__ bias,
                      float*       __restrict__ out)
{
    const int bid = blockIdx.x;
    const int tid = threadIdx.x;

    if (bid < HASH_BLOCKS) {
        // ---------------- hash role ----------------
        __shared__ uint32_t s_xbits[XWORDS_];
        __shared__ int      s_hv[H_ * I_];

        const int b    = bid;
        const int wid  = tid >> 5;
        const int lane = tid & 31;

        // Ballot-pack the 6272-bit x row into 196 smem words.
        const int* xr = x_b + (size_t)b * INPUTS_;
        for (int j = wid; j < XWORDS_; j += 8) {
            int v = xr[j * 32 + lane];
            uint32_t bal = __ballot_sync(0xFFFFFFFFu, v != 0);
            if (lane == 0) s_xbits[j] = bal;
        }
        if (tid < H_ * I_)
            s_hv[tid] = hash_values[tid];
        __syncthreads();

        const int f = tid;
        if (f < F_) {
            const int* ord = input_order + f * I_;
            int h0 = 0, h1 = 0, h2 = 0, h3 = 0;
            #pragma unroll
            for (int i = 0; i < I_; ++i) {
                const int idx = __ldg(&ord[i]);
                const int m = -(int)((s_xbits[idx >> 5] >> (idx & 31)) & 1u);
                h0 ^= s_hv[0 * I_ + i] & m;
                h1 ^= s_hv[1 * I_ + i] & m;
                h2 ^= s_hv[2 * I_ + i] & m;
                h3 ^= s_hv[3 * I_ + i] & m;
            }
            g_hashes[b * F_ + f] = make_int4(h0, h1, h2, h3);
        }

        __threadfence();
        __syncthreads();
        if (tid == 0) atomicAdd(&g_hash_done, 1);

    } else if (bid < HASH_BLOCKS + BUILD_BLOCKS) {
        // ---------------- build role ----------------
        const int bb = bid - HASH_BLOCKS;                 // 0 .. 1791
        const int t  = bb * 256 + tid;                    // 0 .. FE4_-1
        const float4* p = reinterpret_cast<const float4*>(table) + t;

        uint32_t a0[4] = {0,0,0,0};
        uint32_t a1[4] = {0,0,0,0};
        uint32_t a2[4] = {0,0,0,0};
        uint32_t a3[4] = {0,0,0,0};

        #pragma unroll
        for (int c = 0; c < C_; ++c) {
            float4 v = __ldcs(p + (size_t)c * FE4_);
            const uint32_t bit = 1u << (c & 31);
            const int w = c >> 5;                         // compile-time
            if (v.x < 0.0f) a0[w] |= bit;
            if (v.y < 0.0f) a1[w] |= bit;
            if (v.z < 0.0f) a2[w] |= bit;
            if (v.w < 0.0f) a3[w] |= bit;
        }

        uint4* o = reinterpret_cast<uint4*>(g_negw) + (size_t)t * 4;
        o[0] = make_uint4(a0[0], a0[1], a0[2], a0[3]);
        o[1] = make_uint4(a1[0], a1[1], a1[2], a1[3]);
        o[2] = make_uint4(a2[0], a2[1], a2[2], a2[3]);
        o[3] = make_uint4(a3[0], a3[1], a3[2], a3[3]);

        // Publish: this block covers exactly filter f = bb/8 (2048 float4/f).
        __threadfence();
        __syncthreads();
        if (tid == 0) atomicAdd(&g_fdone[bb >> 3], 1);

    } else {
        // ---------------- accum role ----------------
        // 8 warps x 28 filters; one warp-uniform 16B uint4 load per hash;
        // lane owns classes lane+32w. Waits per-filter on g_fdone.
        __shared__ int s_cnt[8 * 132];

        const int b    = bid - (HASH_BLOCKS + BUILD_BLOCKS);
        const int wi   = tid >> 5;
        const int lane = tid & 31;

        // Wait for all hashes (hash blocks dispatched first; near-free).
        while (ld_acquire_gpu(&g_hash_done) != HASH_BLOCKS)
            __nanosleep(128);

        const int4*  hb = g_hashes + b * F_;
        const uint4* nw = reinterpret_cast<const uint4*>(g_negw);

        int c0 = 0, c1 = 0, c2 = 0, c3 = 0;
        const int f0 = wi * (F_ / 8);                     // 28 filters / warp

        #pragma unroll 2
        for (int k = 0; k < F_ / 8; ++k) {
            const int f = f0 + k;
            // Wait until the 8 build blocks for filter f have published.
            while (ld_acquire_gpu(&g_fdone[f]) != 8)
                __nanosleep(128);

            const int4 h = __ldcg(&hb[f]);
            const uint4* base = nw + (size_t)f * E_;
            const uint4 ma = __ldcg(&base[h.x]);
            const uint4 mb = __ldcg(&base[h.y]);
            const uint4 mc = __ldcg(&base[h.z]);
            const uint4 md = __ldcg(&base[h.w]);
            const uint32_t mx = ma.x | mb.x | mc.x | md.x;
            const uint32_t my = ma.y | mb.y | mc.y | md.y;
            const uint32_t mz = ma.z | mb.z | mc.z | md.z;
            const uint32_t mw = ma.w | mb.w | mc.w | md.w;
            c0 += (mx >> lane) & 1;
            c1 += (my >> lane) & 1;
            c2 += (mz >> lane) & 1;
            c3 += (mw >> lane) & 1;
        }

        int* sr = s_cnt + wi * 132;
        sr[lane]      = c0;
        sr[lane + 32] = c1;
        sr[lane + 64] = c2;
        sr[lane + 96] = c3;
        __syncthreads();

        if (tid < 128) {
            int total = 0;
            #pragma unroll
            for (int w = 0; w < 8; ++w)
                total += s_cnt[w * 132 + tid];
            if (tid < C_)
                out[b * C_ + tid] = bias[tid] + (float)(F_ - 2 * total);
        }
    }
}

// ---------------------------------------------------------------------------
// Launch. Input order per metadata: x_b, input_order, hash_values, table, bias
// ---------------------------------------------------------------------------
extern "C" void kernel_launch(void* const* d_in, const int* in_sizes, int n_in,
                              void* d_out, int out_size)
{
    const int*   x_b         = (const int*)  d_in[0];
    const int*   input_order = (const int*)  d_in[1];
    const int*   hash_values = (const int*)  d_in[2];
    const float* table       = (const float*)d_in[3];
    const float* bias        = (const float*)d_in[4];
    float*       out         = (float*)d_out;

    init_flags_kernel<<<1, 256>>>();

    fused_pipeline_kernel<<<HASH_BLOCKS + BUILD_BLOCKS + ACCUM_BLOCKS, 256>>>(
        table, x_b, input_order, hash_values, bias, out);
}

// round 10
// speedup vs baseline: 1.0969x; 1.0969x over previous
#include <cuda_runtime.h>
#include <cstdint>

// Problem constants (fixed shapes from setup_inputs)
#define B_   512
#define C_   100
#define F_   224
#define E_   8192
#define H_   4
#define I_   28
#define INPUTS_ (F_ * I_)          // 6272 == x_b cols, no padding needed
#define FE_  (F_ * E_)             // 1,835,008
#define FE4_ (FE_ / 4)             // 458,752
#define BUILD_BLOCKS (FE4_ / 256)  // 1792
#define XWORDS_ (INPUTS_ / 32)     // 196
#define NSEG_ 4                    // accum f-segments
#define FSEG_ (F_ / NSEG_)         // 56 filters per segment
#define FWARP_ (FSEG_ / 8)         // 7 filters per warp

// Scratch (device globals: allocation-free per harness rules)
// negw[(f*E + e)] : uint4 whose bit c (across 4 words) set <=> table[c][f][e] < 0
__device__ uint32_t g_negw[F_ * E_ * 4];          // 29.36 MB
__device__ int4     g_hashes[B_ * F_];            // 1.8 MB
__device__ int      g_partial[NSEG_ * B_ * 128];  // 1 MB partial counts

// ---------------------------------------------------------------------------
// Fused Phase A + B (identical to the 127.5us version). Blocks [0,BUILD_BLOCKS)
// stream the 734MB table (coalesced float4, evict-first) and pack per-(f,e)
// 100-bit negative masks. Blocks [BUILD_BLOCKS, +512) compute the H3 hashes
// for one batch row each, hiding under the build blocks' DRAM time.
// ---------------------------------------------------------------------------
__global__ void __launch_bounds__(256)
fused_build_hash_kernel(const float* __restrict__ table,
                        const int*   __restrict__ x_b,
                        const int*   __restrict__ input_order,
                        const int*   __restrict__ hash_values)
{
    __shared__ uint32_t s_xbits[XWORDS_];     // 784 B  (packed x row)
    __shared__ int      s_hv[H_ * I_];        // 448 B

    const int bid = blockIdx.x;

    if (bid < BUILD_BLOCKS) {
        // ---------------- build role ----------------
        const int t = bid * 256 + threadIdx.x;            // 0 .. FE4_-1
        const float4* p = reinterpret_cast<const float4*>(table) + t;

        uint32_t a0[4] = {0,0,0,0};
        uint32_t a1[4] = {0,0,0,0};
        uint32_t a2[4] = {0,0,0,0};
        uint32_t a3[4] = {0,0,0,0};

        #pragma unroll
        for (int c = 0; c < C_; ++c) {
            float4 v = __ldcs(p + (size_t)c * FE4_);
            const uint32_t bit = 1u << (c & 31);
            const int w = c >> 5;                         // compile-time
            if (v.x < 0.0f) a0[w] |= bit;
            if (v.y < 0.0f) a1[w] |= bit;
            if (v.z < 0.0f) a2[w] |= bit;
            if (v.w < 0.0f) a3[w] |= bit;
        }

        uint4* out = reinterpret_cast<uint4*>(g_negw) + (size_t)t * 4;
        out[0] = make_uint4(a0[0], a0[1], a0[2], a0[3]);
        out[1] = make_uint4(a1[0], a1[1], a1[2], a1[3]);
        out[2] = make_uint4(a2[0], a2[1], a2[2], a2[3]);
        out[3] = make_uint4(a3[0], a3[1], a3[2], a3[3]);
    } else {
        // ---------------- hash role ----------------
        const int b    = bid - BUILD_BLOCKS;
        const int tid  = threadIdx.x;
        const int wid  = tid >> 5;
        const int lane = tid & 31;

        // Ballot-pack the 6272-bit x row into 196 smem words.
        const int* xr = x_b + (size_t)b * INPUTS_;
        for (int j = wid; j < XWORDS_; j += 8) {
            int v = xr[j * 32 + lane];
            uint32_t bal = __ballot_sync(0xFFFFFFFFu, v != 0);
            if (lane == 0) s_xbits[j] = bal;
        }
        if (tid < H_ * I_)
            s_hv[tid] = hash_values[tid];
        __syncthreads();

        const int f = tid;
        if (f < F_) {
            const int* ord = input_order + f * I_;
            int h0 = 0, h1 = 0, h2 = 0, h3 = 0;
            #pragma unroll
            for (int i = 0; i < I_; ++i) {
                const int idx = __ldg(&ord[i]);
                const int m = -(int)((s_xbits[idx >> 5] >> (idx & 31)) & 1u);
                h0 ^= s_hv[0 * I_ + i] & m;
                h1 ^= s_hv[1 * I_ + i] & m;
                h2 ^= s_hv[2 * I_ + i] & m;
                h3 ^= s_hv[3 * I_ + i] & m;
            }
            g_hashes[b * F_ + f] = make_int4(h0, h1, h2, h3);
        }
    }
}

// ---------------------------------------------------------------------------
// Phase C: accumulate. Block = (batch row b, f-segment seg); 8 warps x 7
// filters each. The block's 56 hashes are staged in smem first (coalesced),
// so each loop iteration's gmem chain is ONE hop (4 independent warp-uniform
// uint4 loads). Partial class counts go to g_partial (deterministic, every
// slot written -> no init needed).
// ---------------------------------------------------------------------------
__global__ void __launch_bounds__(256)
accum_kernel()
{
    __shared__ int4 s_h[FSEG_];          // 56 staged hashes
    __shared__ int  s_cnt[8 * 132];

    const int b    = blockIdx.x;
    const int seg  = blockIdx.y;
    const int tid  = threadIdx.x;
    const int wi   = tid >> 5;
    const int lane = tid & 31;

    // Stage this block's hashes: 56 int4 = 224 ints, coalesced.
    const int* hsrc = reinterpret_cast<const int*>(g_hashes + b * F_ + seg * FSEG_);
    if (tid < FSEG_ * 4)
        reinterpret_cast<int*>(s_h)[tid] = __ldg(&hsrc[tid]);
    __syncthreads();

    const uint4* nw = reinterpret_cast<const uint4*>(g_negw);
    const int fbase = seg * FSEG_ + wi * FWARP_;

    int c0 = 0, c1 = 0, c2 = 0, c3 = 0;

    #pragma unroll
    for (int k = 0; k < FWARP_; ++k) {
        const int4 h = s_h[wi * FWARP_ + k];
        const uint4* base = nw + (size_t)(fbase + k) * E_;
        const uint4 ma = __ldg(&base[h.x]);
        const uint4 mb = __ldg(&base[h.y]);
        const uint4 mc = __ldg(&base[h.z]);
        const uint4 md = __ldg(&base[h.w]);
        const uint32_t mx = ma.x | mb.x | mc.x | md.x;
        const uint32_t my = ma.y | mb.y | mc.y | md.y;
        const uint32_t mz = ma.z | mb.z | mc.z | md.z;
        const uint32_t mw = ma.w | mb.w | mc.w | md.w;
        c0 += (mx >> lane) & 1;
        c1 += (my >> lane) & 1;
        c2 += (mz >> lane) & 1;
        c3 += (mw >> lane) & 1;
    }

    int* sr = s_cnt + wi * 132;
    sr[lane]      = c0;
    sr[lane + 32] = c1;
    sr[lane + 64] = c2;
    sr[lane + 96] = c3;
    __syncthreads();

    if (tid < 128) {
        int total = 0;
        #pragma unroll
        for (int w = 0; w < 8; ++w)
            total += s_cnt[w * 132 + tid];
        g_partial[(seg * B_ + b) * 128 + tid] = total;
    }
}

// ---------------------------------------------------------------------------
// Finalize: sum the NSEG_ partials per (b, c) and add bias.
// out[b][c] = bias[c] + F - 2 * count
// ---------------------------------------------------------------------------
__global__ void __launch_bounds__(128)
finalize_kernel(const float* __restrict__ bias, float* __restrict__ out)
{
    const int b   = blockIdx.x;
    const int tid = threadIdx.x;

    int total = 0;
    #pragma unroll
    for (int s = 0; s < NSEG_; ++s)
        total += g_partial[(s * B_ + b) * 128 + tid];

    if (tid < C_)
        out[b * C_ + tid] = bias[tid] + (float)(F_ - 2 * total);
}

// ---------------------------------------------------------------------------
// Launch. Input order per metadata: x_b, input_order, hash_values, table, bias
// ---------------------------------------------------------------------------
extern "C" void kernel_launch(void* const* d_in, const int* in_sizes, int n_in,
                              void* d_out, int out_size)
{
    const int*   x_b         = (const int*)  d_in[0];
    const int*   input_order = (const int*)  d_in[1];
    const int*   hash_values = (const int*)  d_in[2];
    const float* table       = (const float*)d_in[3];
    const float* bias        = (const float*)d_in[4];
    float*       out         = (float*)d_out;

    // Phase A+B fused: table stream + sign-mask build, hash blocks in the tail
    fused_build_hash_kernel<<<BUILD_BLOCKS + B_, 256>>>(
        table, x_b, input_order, hash_values);

    // Phase C: gather+accumulate from negw (latency-optimized, 4x block split)
    accum_kernel<<<dim3(B_, NSEG_), 256>>>();

    // Combine partials + bias
    finalize_kernel<<<B_, 128>>>(bias, out);
}

// round 12
// speedup vs baseline: 1.1187x; 1.0199x over previous
#include <cuda_runtime.h>
#include <cstdint>

// Problem constants (fixed shapes from setup_inputs)
#define B_   512
#define C_   100
#define F_   224
#define E_   8192
#define H_   4
#define I_   28
#define INPUTS_ (F_ * I_)          // 6272 == x_b cols, no padding needed
#define FE_  (F_ * E_)             // 1,835,008
#define FE4_ (FE_ / 4)             // 458,752
#define BUILD_BLOCKS (FE4_ / 256)  // 1792
#define XWORDS_ (INPUTS_ / 32)     // 196
#define NSEG_ 4                    // accum f-segments
#define FSEG_ (F_ / NSEG_)         // 56 filters per segment
#define FWARP_ (FSEG_ / 8)         // 7 filters per warp

// Scratch (device globals: allocation-free per harness rules)
// negw[(f*E + e)] : uint4 whose bit c (across 4 words) set <=> table[c][f][e] < 0
__device__ __align__(64) uint32_t g_negw[F_ * E_ * 4];   // 29.36 MB, L2-resident
__device__ int4     g_hashes[B_ * F_];            // 1.8 MB
__device__ int      g_partial[NSEG_ * B_ * 128];  // 1 MB partial counts

// 32-byte store with L2 evict-last policy (sm_103 requires .v4.b64 width for
// this modifier). Keeps negw resident in L2 through the table stream so the
// accum phase hits L2 instead of DRAM.
__device__ __forceinline__ void st32_evict_last(void* p,
                                                uint64_t q0, uint64_t q1,
                                                uint64_t q2, uint64_t q3) {
    asm volatile("st.global.L2::evict_last.v4.b64 [%0], {%1,%2,%3,%4};"
                 :: "l"(p), "l"(q0), "l"(q1), "l"(q2), "l"(q3) : "memory");
}

__device__ __forceinline__ uint64_t pk(uint32_t lo, uint32_t hi) {
    return (uint64_t)lo | ((uint64_t)hi << 32);
}

// ---------------------------------------------------------------------------
// Fused Phase A + B. Blocks [0,BUILD_BLOCKS) stream the 734MB table
// (coalesced float4, evict-first) and pack per-(f,e) 100-bit negative masks
// (stored evict-last, 2x32B per thread). Blocks [BUILD_BLOCKS, +512) compute
// the H3 hashes for one batch row each, hiding under the build DRAM time.
// ---------------------------------------------------------------------------
__global__ void __launch_bounds__(256)
fused_build_hash_kernel(const float* __restrict__ table,
                        const int*   __restrict__ x_b,
                        const int*   __restrict__ input_order,
                        const int*   __restrict__ hash_values)
{
    __shared__ uint32_t s_xbits[XWORDS_];     // 784 B  (packed x row)
    __shared__ int      s_hv[H_ * I_];        // 448 B

    const int bid = blockIdx.x;

    if (bid < BUILD_BLOCKS) {
        // ---------------- build role ----------------
        const int t = bid * 256 + threadIdx.x;            // 0 .. FE4_-1
        const float4* p = reinterpret_cast<const float4*>(table) + t;

        uint32_t a0[4] = {0,0,0,0};
        uint32_t a1[4] = {0,0,0,0};
        uint32_t a2[4] = {0,0,0,0};
        uint32_t a3[4] = {0,0,0,0};

        #pragma unroll
        for (int c = 0; c < C_; ++c) {
            float4 v = __ldcs(p + (size_t)c * FE4_);
            const uint32_t bit = 1u << (c & 31);
            const int w = c >> 5;                         // compile-time
            if (v.x < 0.0f) a0[w] |= bit;
            if (v.y < 0.0f) a1[w] |= bit;
            if (v.z < 0.0f) a2[w] |= bit;
            if (v.w < 0.0f) a3[w] |= bit;
        }

        char* out = reinterpret_cast<char*>(g_negw) + (size_t)t * 64;
        st32_evict_last(out,
                        pk(a0[0], a0[1]), pk(a0[2], a0[3]),
                        pk(a1[0], a1[1]), pk(a1[2], a1[3]));
        st32_evict_last(out + 32,
                        pk(a2[0], a2[1]), pk(a2[2], a2[3]),
                        pk(a3[0], a3[1]), pk(a3[2], a3[3]));
    } else {
        // ---------------- hash role ----------------
        const int b    = bid - BUILD_BLOCKS;
        const int tid  = threadIdx.x;
        const int wid  = tid >> 5;
        const int lane = tid & 31;

        // Ballot-pack the 6272-bit x row into 196 smem words.
        const int* xr = x_b + (size_t)b * INPUTS_;
        for (int j = wid; j < XWORDS_; j += 8) {
            int v = xr[j * 32 + lane];
            uint32_t bal = __ballot_sync(0xFFFFFFFFu, v != 0);
            if (lane == 0) s_xbits[j] = bal;
        }
        if (tid < H_ * I_)
            s_hv[tid] = hash_values[tid];
        __syncthreads();

        const int f = tid;
        if (f < F_) {
            const int* ord = input_order + f * I_;
            int h0 = 0, h1 = 0, h2 = 0, h3 = 0;
            #pragma unroll
            for (int i = 0; i < I_; ++i) {
                const int idx = __ldg(&ord[i]);
                const int m = -(int)((s_xbits[idx >> 5] >> (idx & 31)) & 1u);
                h0 ^= s_hv[0 * I_ + i] & m;
                h1 ^= s_hv[1 * I_ + i] & m;
                h2 ^= s_hv[2 * I_ + i] & m;
                h3 ^= s_hv[3 * I_ + i] & m;
            }
            g_hashes[b * F_ + f] = make_int4(h0, h1, h2, h3);
        }
    }
}

// ---------------------------------------------------------------------------
// Phase C: accumulate. Block = (batch row b, f-segment seg); 8 warps x 7
// filters each. The block's 56 hashes are staged in smem first (coalesced),
// so each loop iteration's gmem chain is ONE hop (4 independent warp-uniform
// uint4 loads — L2 hits thanks to evict-last negw). Partial class counts go
// to g_partial (deterministic, every slot written -> no init needed).
// ---------------------------------------------------------------------------
__global__ void __launch_bounds__(256)
accum_kernel()
{
    __shared__ int4 s_h[FSEG_];          // 56 staged hashes
    __shared__ int  s_cnt[8 * 132];

    const int b    = blockIdx.x;
    const int seg  = blockIdx.y;
    const int tid  = threadIdx.x;
    const int wi   = tid >> 5;
    const int lane = tid & 31;

    // Stage this block's hashes: 56 int4 = 224 ints, coalesced.
    const int* hsrc = reinterpret_cast<const int*>(g_hashes + b * F_ + seg * FSEG_);
    if (tid < FSEG_ * 4)
        reinterpret_cast<int*>(s_h)[tid] = __ldg(&hsrc[tid]);
    __syncthreads();

    const uint4* nw = reinterpret_cast<const uint4*>(g_negw);
    const int fbase = seg * FSEG_ + wi * FWARP_;

    int c0 = 0, c1 = 0, c2 = 0, c3 = 0;

    #pragma unroll
    for (int k = 0; k < FWARP_; ++k) {
        const int4 h = s_h[wi * FWARP_ + k];
        const uint4* base = nw + (size_t)(fbase + k) * E_;
        const uint4 ma = __ldg(&base[h.x]);
        const uint4 mb = __ldg(&base[h.y]);
        const uint4 mc = __ldg(&base[h.z]);
        const uint4 md = __ldg(&base[h.w]);
        const uint32_t mx = ma.x | mb.x | mc.x | md.x;
        const uint32_t my = ma.y | mb.y | mc.y | md.y;
        const uint32_t mz = ma.z | mb.z | mc.z | md.z;
        const uint32_t mw = ma.w | mb.w | mc.w | md.w;
        c0 += (mx >> lane) & 1;
        c1 += (my >> lane) & 1;
        c2 += (mz >> lane) & 1;
        c3 += (mw >> lane) & 1;
    }

    int* sr = s_cnt + wi * 132;
    sr[lane]      = c0;
    sr[lane + 32] = c1;
    sr[lane + 64] = c2;
    sr[lane + 96] = c3;
    __syncthreads();

    if (tid < 128) {
        int total = 0;
        #pragma unroll
        for (int w = 0; w < 8; ++w)
            total += s_cnt[w * 132 + tid];
        g_partial[(seg * B_ + b) * 128 + tid] = total;
    }
}

// ---------------------------------------------------------------------------
// Finalize: sum the NSEG_ partials per (b, c) and add bias.
// out[b][c] = bias[c] + F - 2 * count
// ---------------------------------------------------------------------------
__global__ void __launch_bounds__(128)
finalize_kernel(const float* __restrict__ bias, float* __restrict__ out)
{
    const int b   = blockIdx.x;
    const int tid = threadIdx.x;

    int total = 0;
    #pragma unroll
    for (int s = 0; s < NSEG_; ++s)
        total += g_partial[(s * B_ + b) * 128 + tid];

    if (tid < C_)
        out[b * C_ + tid] = bias[tid] + (float)(F_ - 2 * total);
}

// ---------------------------------------------------------------------------
// Launch. Input order per metadata: x_b, input_order, hash_values, table, bias
// ---------------------------------------------------------------------------
extern "C" void kernel_launch(void* const* d_in, const int* in_sizes, int n_in,
                              void* d_out, int out_size)
{
    const int*   x_b         = (const int*)  d_in[0];
    const int*   input_order = (const int*)  d_in[1];
    const int*   hash_values = (const int*)  d_in[2];
    const float* table       = (const float*)d_in[3];
    const float* bias        = (const float*)d_in[4];
    float*       out         = (float*)d_out;

    // Phase A+B fused: table stream + sign-mask build, hash blocks in the tail
    fused_build_hash_kernel<<<BUILD_BLOCKS + B_, 256>>>(
        table, x_b, input_order, hash_values);

    // Phase C: gather+accumulate from L2-resident negw
    accum_kernel<<<dim3(B_, NSEG_), 256>>>();

    // Combine partials + bias
    finalize_kernel<<<B_, 128>>>(bias, out);
}